// round 5
// baseline (speedup 1.0000x reference)
#include <cuda_runtime.h>

// MaskedMSE: B=16, C=4, H=W=512  — single fused kernel.
// input : d_in[0]  float32 [16, 4, 512, 512]
// target: d_in[1]  float32 [16, 5, 512, 512]  (channel 4 is the {0,1} mask)
// out   : d_out    float32 [1]
//
// 16 x 64 blocks each produce a per-(batch, block) (masked SSE, mask count)
// partial. The last block to finish (elected via atomic ticket; floats are
// never touched atomically, so the result is deterministic) folds all 1024
// partials in a fixed order, applies per_b = cnt>0 ? sse/(C*cnt) : 0,
// means over B, and resets the ticket for the next graph replay.

#define HW      262144          // 512*512
#define HW4     65536           // HW / 4 (float4 units)
#define CH      4
#define BATCH   16
#define BPB     64              // blocks per batch
#define TPB     256             // threads per block
#define NBLK    (BATCH * BPB)   // 1024

__device__ float2       g_partials[NBLK];
__device__ unsigned int g_ticket = 0;

__global__ __launch_bounds__(TPB) void masked_mse_fused(
    const float* __restrict__ input,
    const float* __restrict__ target,
    float* __restrict__ out)
{
    const int b   = blockIdx.y;
    const int tid = threadIdx.x;

    const float4* __restrict__ inb = (const float4*)(input  + (size_t)b * CH * HW);
    const float4* __restrict__ tgb = (const float4*)(target + (size_t)b * (CH + 1) * HW);
    const float4* __restrict__ mb  = (const float4*)(target + (size_t)b * (CH + 1) * HW + (size_t)CH * HW);

    float sse = 0.0f;
    float cnt = 0.0f;

    // 65536 vec4 per batch / (64 blocks * 256 threads) = 4 iterations/thread
    for (int p = blockIdx.x * TPB + tid; p < HW4; p += BPB * TPB) {
        const float4 m = mb[p];
        cnt += m.x + m.y + m.z + m.w;
        #pragma unroll
        for (int c = 0; c < CH; c++) {
            const float4 a = inb[c * HW4 + p];
            const float4 t = tgb[c * HW4 + p];
            const float dx = a.x - t.x;
            const float dy = a.y - t.y;
            const float dz = a.z - t.z;
            const float dw = a.w - t.w;
            sse += m.x * (dx * dx);
            sse += m.y * (dy * dy);
            sse += m.z * (dz * dz);
            sse += m.w * (dw * dw);
        }
    }

    // intra-warp reduce
    #pragma unroll
    for (int o = 16; o > 0; o >>= 1) {
        sse += __shfl_down_sync(0xFFFFFFFFu, sse, o);
        cnt += __shfl_down_sync(0xFFFFFFFFu, cnt, o);
    }

    __shared__ float s_sse[TPB / 32];
    __shared__ float s_cnt[TPB / 32];
    __shared__ bool  s_is_last;
    const int lane = tid & 31;
    const int wid  = tid >> 5;
    if (lane == 0) { s_sse[wid] = sse; s_cnt[wid] = cnt; }
    __syncthreads();

    if (wid == 0) {
        sse = (lane < TPB / 32) ? s_sse[lane] : 0.0f;
        cnt = (lane < TPB / 32) ? s_cnt[lane] : 0.0f;
        #pragma unroll
        for (int o = 4; o > 0; o >>= 1) {
            sse += __shfl_down_sync(0xFFFFFFFFu, sse, o);
            cnt += __shfl_down_sync(0xFFFFFFFFu, cnt, o);
        }
        if (lane == 0) {
            g_partials[b * BPB + blockIdx.x] = make_float2(sse, cnt);
            __threadfence();
            const unsigned int t = atomicAdd(&g_ticket, 1u);
            s_is_last = (t == NBLK - 1);
        }
    }
    __syncthreads();

    if (!s_is_last) return;

    // ---- last block: fold all partials (fixed order -> deterministic) ----
    __threadfence();  // acquire: make all blocks' partials visible

    // 8 warps; warp w handles batches 2w and 2w+1.
    __shared__ float s_per_b[BATCH];
    #pragma unroll
    for (int i = 0; i < 2; i++) {
        const int bb = wid * 2 + i;
        const float2 p0 = g_partials[bb * BPB + lane];
        const float2 p1 = g_partials[bb * BPB + lane + 32];
        float bs = p0.x + p1.x;
        float bc = p0.y + p1.y;
        #pragma unroll
        for (int o = 16; o > 0; o >>= 1) {
            bs += __shfl_down_sync(0xFFFFFFFFu, bs, o);
            bc += __shfl_down_sync(0xFFFFFFFFu, bc, o);
        }
        if (lane == 0)
            s_per_b[bb] = (bc > 0.0f) ? bs / ((float)CH * bc) : 0.0f;
    }
    __syncthreads();

    if (tid == 0) {
        float total = 0.0f;
        #pragma unroll
        for (int i = 0; i < BATCH; i++) total += s_per_b[i];
        out[0] = total / (float)BATCH;
        g_ticket = 0;   // reset for next graph replay
    }
}

extern "C" void kernel_launch(void* const* d_in, const int* in_sizes, int n_in,
                              void* d_out, int out_size)
{
    const float* input  = (const float*)d_in[0];
    const float* target = (const float*)d_in[1];
    float*       out    = (float*)d_out;

    dim3 grid(BPB, BATCH);
    masked_mse_fused<<<grid, TPB>>>(input, target, out);
}

// round 8
// speedup vs baseline: 1.1175x; 1.1175x over previous
#include <cuda_runtime.h>

// MaskedMSE: B=16, C=4, H=W=512 — two kernels, finalize overlapped via PDL.
// input : d_in[0]  float32 [16, 4, 512, 512]
// target: d_in[1]  float32 [16, 5, 512, 512]  (channel 4 is the {0,1} mask)
// out   : d_out    float32 [1]
//
// Stage 1: 16 x BPB blocks -> per-(batch, block) (masked SSE, mask count)
//          partials in a __device__ scratch array (deterministic, no atomics).
// Stage 2: launched with programmatic stream serialization (PDL). Its warps
//          become resident while stage 1 runs and block in
//          cudaGridDependencySynchronize(); launch latency is hidden.

#define HW      262144          // 512*512
#define HW4     65536           // HW / 4 (float4 units)
#define CH      4
#define BATCH   16
#define BPB     64              // blocks per batch
#define TPB     256             // threads per block

__device__ float2 g_partials[BATCH * BPB];

__global__ __launch_bounds__(TPB) void masked_mse_partials(
    const float* __restrict__ input,
    const float* __restrict__ target)
{
    const int b   = blockIdx.y;
    const int tid = threadIdx.x;

    const float4* __restrict__ inb = (const float4*)(input  + (size_t)b * CH * HW);
    const float4* __restrict__ tgb = (const float4*)(target + (size_t)b * (CH + 1) * HW);
    const float4* __restrict__ mb  = (const float4*)(target + (size_t)b * (CH + 1) * HW + (size_t)CH * HW);

    float sse = 0.0f;
    float cnt = 0.0f;

    // 65536 vec4 per batch / (64 blocks * 256 threads) = 4 iterations/thread
    for (int p = blockIdx.x * TPB + tid; p < HW4; p += BPB * TPB) {
        const float4 m = mb[p];
        cnt += m.x + m.y + m.z + m.w;
        #pragma unroll
        for (int c = 0; c < CH; c++) {
            const float4 a = inb[c * HW4 + p];
            const float4 t = tgb[c * HW4 + p];
            const float dx = a.x - t.x;
            const float dy = a.y - t.y;
            const float dz = a.z - t.z;
            const float dw = a.w - t.w;
            sse += m.x * (dx * dx);
            sse += m.y * (dy * dy);
            sse += m.z * (dz * dz);
            sse += m.w * (dw * dw);
        }
    }

    // intra-warp reduce
    #pragma unroll
    for (int o = 16; o > 0; o >>= 1) {
        sse += __shfl_down_sync(0xFFFFFFFFu, sse, o);
        cnt += __shfl_down_sync(0xFFFFFFFFu, cnt, o);
    }

    __shared__ float s_sse[TPB / 32];
    __shared__ float s_cnt[TPB / 32];
    const int lane = tid & 31;
    const int wid  = tid >> 5;
    if (lane == 0) { s_sse[wid] = sse; s_cnt[wid] = cnt; }
    __syncthreads();

    if (wid == 0) {
        sse = (lane < TPB / 32) ? s_sse[lane] : 0.0f;
        cnt = (lane < TPB / 32) ? s_cnt[lane] : 0.0f;
        #pragma unroll
        for (int o = 4; o > 0; o >>= 1) {
            sse += __shfl_down_sync(0xFFFFFFFFu, sse, o);
            cnt += __shfl_down_sync(0xFFFFFFFFu, cnt, o);
        }
        if (lane == 0)
            g_partials[b * BPB + blockIdx.x] = make_float2(sse, cnt);
    }
}

__global__ void masked_mse_finalize(float* __restrict__ out)
{
    // PDL: wait for the producer grid to fully complete (and its writes to
    // become visible) — but this block is already resident, so the launch
    // latency of this kernel is overlapped with stage 1's execution.
    cudaGridDependencySynchronize();

    // 16 warps, warp w owns batch w: reduce its 64 partials in fixed order.
    const int w    = threadIdx.x >> 5;
    const int lane = threadIdx.x & 31;

    const float2 p0 = g_partials[w * BPB + lane];
    const float2 p1 = g_partials[w * BPB + lane + 32];
    float sse = p0.x + p1.x;
    float cnt = p0.y + p1.y;

    #pragma unroll
    for (int o = 16; o > 0; o >>= 1) {
        sse += __shfl_down_sync(0xFFFFFFFFu, sse, o);
        cnt += __shfl_down_sync(0xFFFFFFFFu, cnt, o);
    }

    __shared__ float per_b[BATCH];
    if (lane == 0)
        per_b[w] = (cnt > 0.0f) ? sse / ((float)CH * cnt) : 0.0f;
    __syncthreads();

    if (threadIdx.x == 0) {
        float total = 0.0f;
        #pragma unroll
        for (int i = 0; i < BATCH; i++) total += per_b[i];
        out[0] = total / (float)BATCH;
    }
}

extern "C" void kernel_launch(void* const* d_in, const int* in_sizes, int n_in,
                              void* d_out, int out_size)
{
    const float* input  = (const float*)d_in[0];
    const float* target = (const float*)d_in[1];
    float*       out    = (float*)d_out;

    dim3 grid(BPB, BATCH);
    masked_mse_partials<<<grid, TPB>>>(input, target);

    // Finalize with programmatic stream serialization: may begin execution
    // before stage 1 completes; correctness is enforced by the
    // cudaGridDependencySynchronize() inside the kernel.
    cudaLaunchConfig_t cfg = {};
    cfg.gridDim  = dim3(1, 1, 1);
    cfg.blockDim = dim3(BATCH * 32, 1, 1);
    cfg.dynamicSmemBytes = 0;
    cfg.stream = 0;
    cudaLaunchAttribute attr[1];
    attr[0].id = cudaLaunchAttributeProgrammaticStreamSerialization;
    attr[0].val.programmaticStreamSerializationAllowed = 1;
    cfg.attrs = attr;
    cfg.numAttrs = 1;
    cudaLaunchKernelEx(&cfg, masked_mse_finalize, out);
}